// round 2
// baseline (speedup 1.0000x reference)
#include <cuda_runtime.h>
#include <math.h>

#define DIMM   1024
#define NHEADS 16
#define HDIM   64
#define BATCH  2
#define SEQ    2048
#define MROWS  (BATCH*SEQ)   // 4096
#define QKSCALE 0.125f       // 1/sqrt(64)

// ---------------- scratch (no allocs allowed) ----------------
__device__ float g_q[BATCH*NHEADS*SEQ*HDIM];   // [b][h][s][d]
__device__ float g_k[BATCH*NHEADS*SEQ*HDIM];
__device__ float g_v[BATCH*NHEADS*SEQ*HDIM];
__device__ float g_ctx[MROWS*DIMM];            // [b*s][h*64+d]

// ---------------------------------------------------------------------------
// Generic fp32 GEMM: C[M,N] = A[M,K] @ B[N,K]^T + bias[N]
// BM=BN=128, BK=8, 256 threads, 8x8 per-thread microtile.
// MODE 0: C row-major. MODE 1: scatter into g_q/g_k/g_v. MODE 2: A := g_ctx, C row-major.
// ---------------------------------------------------------------------------
template<int MODE>
__global__ __launch_bounds__(256, 2)
void sgemm_abT(const float* __restrict__ A, const float* __restrict__ Bm,
               const float* __restrict__ bias, float* __restrict__ C,
               int M, int N, int K)
{
    __shared__ float As[8][132];
    __shared__ float Bs[8][132];

    const float* Aptr = (MODE == 2) ? (const float*)g_ctx : A;

    int tid = threadIdx.x;
    int tx  = tid & 15;
    int ty  = tid >> 4;
    int bm  = blockIdx.y * 128;
    int bn  = blockIdx.x * 128;

    int lrow = tid >> 1;          // 0..127
    int lk   = (tid & 1) * 4;     // 0 or 4

    const float* Ag = Aptr + (size_t)(bm + lrow) * K + lk;
    const float* Bg = Bm   + (size_t)(bn + lrow) * K + lk;

    float acc[8][8];
#pragma unroll
    for (int i = 0; i < 8; i++)
#pragma unroll
        for (int j = 0; j < 8; j++) acc[i][j] = 0.f;

    for (int kt = 0; kt < K; kt += 8) {
        float4 av = *(const float4*)(Ag + kt);
        float4 bv = *(const float4*)(Bg + kt);
        __syncthreads();
        As[lk+0][lrow] = av.x; As[lk+1][lrow] = av.y;
        As[lk+2][lrow] = av.z; As[lk+3][lrow] = av.w;
        Bs[lk+0][lrow] = bv.x; Bs[lk+1][lrow] = bv.y;
        Bs[lk+2][lrow] = bv.z; Bs[lk+3][lrow] = bv.w;
        __syncthreads();
#pragma unroll
        for (int kk = 0; kk < 8; kk++) {
            float4 a0 = *(const float4*)&As[kk][ty*8];
            float4 a1 = *(const float4*)&As[kk][ty*8+4];
            float4 b0 = *(const float4*)&Bs[kk][tx*8];
            float4 b1 = *(const float4*)&Bs[kk][tx*8+4];
            float ar[8] = {a0.x,a0.y,a0.z,a0.w,a1.x,a1.y,a1.z,a1.w};
            float br[8] = {b0.x,b0.y,b0.z,b0.w,b1.x,b1.y,b1.z,b1.w};
#pragma unroll
            for (int i = 0; i < 8; i++)
#pragma unroll
                for (int j = 0; j < 8; j++)
                    acc[i][j] = fmaf(ar[i], br[j], acc[i][j]);
        }
    }

#pragma unroll
    for (int i = 0; i < 8; i++) {
        int m = bm + ty*8 + i;
#pragma unroll
        for (int j = 0; j < 8; j++) {
            int n = bn + tx*8 + j;
            float v = acc[i][j] + bias[n];
            if (MODE == 0 || MODE == 2) {
                C[(size_t)m * N + n] = v;
            } else {
                int t = n >> 10;          // which of q/k/v
                int r = n & 1023;
                int h = r >> 6;
                int d = r & 63;
                int b = m >> 11;
                int s = m & 2047;
                float* dst = (t == 0) ? g_q : (t == 1) ? g_k : g_v;
                dst[(((size_t)(b*NHEADS + h))*SEQ + s)*HDIM + d] = v;
            }
        }
    }
}

// ---------------------------------------------------------------------------
// Flash attention (fp32): one block = 64 queries of one (b,h).
// Streams 64-wide K/V tiles with online softmax. 256 threads, 4x4 microtiles.
// smem (dynamic): Qs[64][68] (d-major), Ks[64][68] (d-major), Ps[64][68] (k-major), Vs[64][64]
// ---------------------------------------------------------------------------
__global__ __launch_bounds__(256, 3)
void attn_kernel()
{
    extern __shared__ float sm[];
    float (*Qs)[68] = (float(*)[68])(sm);
    float (*Ks)[68] = (float(*)[68])(sm + 64*68);
    float (*Ps)[68] = (float(*)[68])(sm + 2*64*68);
    float (*Vs)[64] = (float(*)[64])(sm + 3*64*68);

    int tid = threadIdx.x;
    int tx  = tid & 15;
    int ty  = tid >> 4;
    int bh  = blockIdx.y;                 // b*16 + h
    int q0  = blockIdx.x * 64;

    const float* Qg = g_q + (size_t)bh * SEQ * HDIM;
    const float* Kg = g_k + (size_t)bh * SEQ * HDIM;
    const float* Vg = g_v + (size_t)bh * SEQ * HDIM;

    // Load Q tile transposed ([d][r]), pre-scaled by 1/sqrt(Dh).
    for (int idx = tid; idx < 64*16; idx += 256) {
        int r  = idx & 63;
        int d4 = (idx >> 6) * 4;
        float4 v = *(const float4*)(Qg + (size_t)(q0 + r) * HDIM + d4);
        Qs[d4+0][r] = v.x * QKSCALE;
        Qs[d4+1][r] = v.y * QKSCALE;
        Qs[d4+2][r] = v.z * QKSCALE;
        Qs[d4+3][r] = v.w * QKSCALE;
    }

    float mrow[4], lrow[4], o[4][4];
#pragma unroll
    for (int i = 0; i < 4; i++) {
        mrow[i] = -INFINITY; lrow[i] = 0.f;
#pragma unroll
        for (int j = 0; j < 4; j++) o[i][j] = 0.f;
    }

    for (int kt = 0; kt < SEQ; kt += 64) {
        __syncthreads();   // prev-iter consumers of Ks/Vs/Ps done; Qs ready (1st iter)
        // K tile transposed ([d][c])
        for (int idx = tid; idx < 64*16; idx += 256) {
            int c  = idx & 63;
            int d4 = (idx >> 6) * 4;
            float4 v = *(const float4*)(Kg + (size_t)(kt + c) * HDIM + d4);
            Ks[d4+0][c] = v.x; Ks[d4+1][c] = v.y;
            Ks[d4+2][c] = v.z; Ks[d4+3][c] = v.w;
        }
        // V tile natural ([k][d])
        for (int idx = tid; idx < 64*16; idx += 256) {
            int r  = idx >> 4;
            int d4 = (idx & 15) * 4;
            *(float4*)&Vs[r][d4] = *(const float4*)(Vg + (size_t)(kt + r) * HDIM + d4);
        }
        __syncthreads();

        // S = (Q*scale) @ K^T  -> s[4][4]
        float s[4][4];
#pragma unroll
        for (int i = 0; i < 4; i++)
#pragma unroll
            for (int j = 0; j < 4; j++) s[i][j] = 0.f;
#pragma unroll 16
        for (int kk = 0; kk < HDIM; kk++) {
            float4 qv = *(const float4*)&Qs[kk][ty*4];
            float4 kv = *(const float4*)&Ks[kk][tx*4];
            float qr[4] = {qv.x,qv.y,qv.z,qv.w};
            float kr[4] = {kv.x,kv.y,kv.z,kv.w};
#pragma unroll
            for (int i = 0; i < 4; i++)
#pragma unroll
                for (int j = 0; j < 4; j++)
                    s[i][j] = fmaf(qr[i], kr[j], s[i][j]);
        }

        // online softmax (rows split across 16 tx lanes; lane-aligned 16-groups)
#pragma unroll
        for (int i = 0; i < 4; i++) {
            float rmax = fmaxf(fmaxf(s[i][0], s[i][1]), fmaxf(s[i][2], s[i][3]));
#pragma unroll
            for (int ofs = 8; ofs > 0; ofs >>= 1)
                rmax = fmaxf(rmax, __shfl_xor_sync(0xffffffffu, rmax, ofs));
            float mnew  = fmaxf(mrow[i], rmax);
            float alpha = __expf(mrow[i] - mnew);
            float rsum = 0.f;
#pragma unroll
            for (int j = 0; j < 4; j++) {
                s[i][j] = __expf(s[i][j] - mnew);
                rsum += s[i][j];
            }
#pragma unroll
            for (int ofs = 8; ofs > 0; ofs >>= 1)
                rsum += __shfl_xor_sync(0xffffffffu, rsum, ofs);
            lrow[i] = lrow[i] * alpha + rsum;
#pragma unroll
            for (int j = 0; j < 4; j++) o[i][j] *= alpha;
            mrow[i] = mnew;
        }

        // stage P transposed ([k][r])
#pragma unroll
        for (int i = 0; i < 4; i++)
#pragma unroll
            for (int j = 0; j < 4; j++)
                Ps[tx*4+j][ty*4+i] = s[i][j];
        __syncthreads();

        // O += P @ V
#pragma unroll 16
        for (int kk = 0; kk < 64; kk++) {
            float4 pv = *(const float4*)&Ps[kk][ty*4];
            float4 vv = *(const float4*)&Vs[kk][tx*4];
            float pr[4] = {pv.x,pv.y,pv.z,pv.w};
            float vr[4] = {vv.x,vv.y,vv.z,vv.w};
#pragma unroll
            for (int i = 0; i < 4; i++)
#pragma unroll
                for (int j = 0; j < 4; j++)
                    o[i][j] = fmaf(pr[i], vr[j], o[i][j]);
        }
    }

    // epilogue: normalize + write ctx [b][s][h*64+d]
    int b = bh >> 4;
    int h = bh & 15;
#pragma unroll
    for (int i = 0; i < 4; i++) {
        float inv = 1.f / lrow[i];
        int srow = q0 + ty*4 + i;
        size_t base = ((size_t)(b*SEQ + srow))*DIMM + h*HDIM + tx*4;
#pragma unroll
        for (int j = 0; j < 4; j++)
            g_ctx[base + j] = o[i][j] * inv;
    }
}

// ---------------------------------------------------------------------------
extern "C" void kernel_launch(void* const* d_in, const int* in_sizes, int n_in,
                              void* d_out, int out_size)
{
    const float* x      = (const float*)d_in[0];
    const float* qkv_w  = (const float*)d_in[1];
    const float* qkv_b  = (const float*)d_in[2];
    const float* proj_w = (const float*)d_in[3];
    const float* proj_b = (const float*)d_in[4];
    float* out = (float*)d_out;

    (void)in_sizes; (void)n_in; (void)out_size;

    static const int ATTN_SMEM = (3*64*68 + 64*64) * (int)sizeof(float);  // 68608 B
    cudaFuncSetAttribute(attn_kernel, cudaFuncAttributeMaxDynamicSharedMemorySize, ATTN_SMEM);

    dim3 blk(256);
    // 1) QKV projection, scattered into q/k/v scratch
    sgemm_abT<1><<<dim3(3*DIMM/128, MROWS/128), blk>>>(x, qkv_w, qkv_b, nullptr,
                                                       MROWS, 3*DIMM, DIMM);
    // 2) attention
    attn_kernel<<<dim3(SEQ/64, BATCH*NHEADS), blk, ATTN_SMEM>>>();
    // 3) output projection
    sgemm_abT<2><<<dim3(DIMM/128, MROWS/128), blk>>>(nullptr, proj_w, proj_b, out,
                                                     MROWS, DIMM, DIMM);
}

// round 3
// speedup vs baseline: 1.0008x; 1.0008x over previous
#include <cuda_runtime.h>
#include <math.h>

#define DIMM   1024
#define NHEADS 16
#define HDIM   64
#define BATCH  2
#define SEQ    2048
#define MROWS  (BATCH*SEQ)   // 4096
#define QKSCALE 0.125f       // 1/sqrt(64)

// ---------------- scratch (no allocs allowed) ----------------
__device__ float g_q[BATCH*NHEADS*SEQ*HDIM];   // [b][h][s][d]
__device__ float g_k[BATCH*NHEADS*SEQ*HDIM];
__device__ float g_v[BATCH*NHEADS*SEQ*HDIM];
__device__ float g_ctx[MROWS*DIMM];            // [b*s][h*64+d]

// ---------------------------------------------------------------------------
// Generic fp32 GEMM: C[M,N] = A[M,K] @ B[N,K]^T + bias[N]
// BM=BN=128, BK=8, 256 threads, 8x8 per-thread microtile.
// MODE 0: C row-major. MODE 1: scatter into g_q/g_k/g_v. MODE 2: A := g_ctx, C row-major.
// ---------------------------------------------------------------------------
template<int MODE>
__global__ __launch_bounds__(256, 2)
void sgemm_abT(const float* __restrict__ A, const float* __restrict__ Bm,
               const float* __restrict__ bias, float* __restrict__ C,
               int M, int N, int K)
{
    __shared__ float As[8][132];
    __shared__ float Bs[8][132];

    const float* Aptr = (MODE == 2) ? (const float*)g_ctx : A;

    int tid = threadIdx.x;
    int tx  = tid & 15;
    int ty  = tid >> 4;
    int bm  = blockIdx.y * 128;
    int bn  = blockIdx.x * 128;

    int lrow = tid >> 1;          // 0..127
    int lk   = (tid & 1) * 4;     // 0 or 4

    const float* Ag = Aptr + (size_t)(bm + lrow) * K + lk;
    const float* Bg = Bm   + (size_t)(bn + lrow) * K + lk;

    float acc[8][8];
#pragma unroll
    for (int i = 0; i < 8; i++)
#pragma unroll
        for (int j = 0; j < 8; j++) acc[i][j] = 0.f;

    for (int kt = 0; kt < K; kt += 8) {
        float4 av = *(const float4*)(Ag + kt);
        float4 bv = *(const float4*)(Bg + kt);
        __syncthreads();
        As[lk+0][lrow] = av.x; As[lk+1][lrow] = av.y;
        As[lk+2][lrow] = av.z; As[lk+3][lrow] = av.w;
        Bs[lk+0][lrow] = bv.x; Bs[lk+1][lrow] = bv.y;
        Bs[lk+2][lrow] = bv.z; Bs[lk+3][lrow] = bv.w;
        __syncthreads();
#pragma unroll
        for (int kk = 0; kk < 8; kk++) {
            float4 a0 = *(const float4*)&As[kk][ty*8];
            float4 a1 = *(const float4*)&As[kk][ty*8+4];
            float4 b0 = *(const float4*)&Bs[kk][tx*8];
            float4 b1 = *(const float4*)&Bs[kk][tx*8+4];
            float ar[8] = {a0.x,a0.y,a0.z,a0.w,a1.x,a1.y,a1.z,a1.w};
            float br[8] = {b0.x,b0.y,b0.z,b0.w,b1.x,b1.y,b1.z,b1.w};
#pragma unroll
            for (int i = 0; i < 8; i++)
#pragma unroll
                for (int j = 0; j < 8; j++)
                    acc[i][j] = fmaf(ar[i], br[j], acc[i][j]);
        }
    }

#pragma unroll
    for (int i = 0; i < 8; i++) {
        int m = bm + ty*8 + i;
#pragma unroll
        for (int j = 0; j < 8; j++) {
            int n = bn + tx*8 + j;
            float v = acc[i][j] + bias[n];
            if (MODE == 0 || MODE == 2) {
                C[(size_t)m * N + n] = v;
            } else {
                int t = n >> 10;          // which of q/k/v
                int r = n & 1023;
                int h = r >> 6;
                int d = r & 63;
                int b = m >> 11;
                int s = m & 2047;
                float* dst = (t == 0) ? g_q : (t == 1) ? g_k : g_v;
                dst[(((size_t)(b*NHEADS + h))*SEQ + s)*HDIM + d] = v;
            }
        }
    }
}

// ---------------------------------------------------------------------------
// Flash attention (fp32): one block = 64 queries of one (b,h).
// Streams 64-wide K/V tiles with online softmax. 256 threads, 4x4 microtiles.
// smem (dynamic): Qs[64][68] (d-major), Ks[64][68] (d-major), Ps[64][68] (k-major), Vs[64][64]
// ---------------------------------------------------------------------------
__global__ __launch_bounds__(256, 3)
void attn_kernel()
{
    extern __shared__ float sm[];
    float (*Qs)[68] = (float(*)[68])(sm);
    float (*Ks)[68] = (float(*)[68])(sm + 64*68);
    float (*Ps)[68] = (float(*)[68])(sm + 2*64*68);
    float (*Vs)[64] = (float(*)[64])(sm + 3*64*68);

    int tid = threadIdx.x;
    int tx  = tid & 15;
    int ty  = tid >> 4;
    int bh  = blockIdx.y;                 // b*16 + h
    int q0  = blockIdx.x * 64;

    const float* Qg = g_q + (size_t)bh * SEQ * HDIM;
    const float* Kg = g_k + (size_t)bh * SEQ * HDIM;
    const float* Vg = g_v + (size_t)bh * SEQ * HDIM;

    // Load Q tile transposed ([d][r]), pre-scaled by 1/sqrt(Dh).
    for (int idx = tid; idx < 64*16; idx += 256) {
        int r  = idx & 63;
        int d4 = (idx >> 6) * 4;
        float4 v = *(const float4*)(Qg + (size_t)(q0 + r) * HDIM + d4);
        Qs[d4+0][r] = v.x * QKSCALE;
        Qs[d4+1][r] = v.y * QKSCALE;
        Qs[d4+2][r] = v.z * QKSCALE;
        Qs[d4+3][r] = v.w * QKSCALE;
    }

    float mrow[4], lrow[4], o[4][4];
#pragma unroll
    for (int i = 0; i < 4; i++) {
        mrow[i] = -INFINITY; lrow[i] = 0.f;
#pragma unroll
        for (int j = 0; j < 4; j++) o[i][j] = 0.f;
    }

    for (int kt = 0; kt < SEQ; kt += 64) {
        __syncthreads();   // prev-iter consumers of Ks/Vs/Ps done; Qs ready (1st iter)
        // K tile transposed ([d][c])
        for (int idx = tid; idx < 64*16; idx += 256) {
            int c  = idx & 63;
            int d4 = (idx >> 6) * 4;
            float4 v = *(const float4*)(Kg + (size_t)(kt + c) * HDIM + d4);
            Ks[d4+0][c] = v.x; Ks[d4+1][c] = v.y;
            Ks[d4+2][c] = v.z; Ks[d4+3][c] = v.w;
        }
        // V tile natural ([k][d])
        for (int idx = tid; idx < 64*16; idx += 256) {
            int r  = idx >> 4;
            int d4 = (idx & 15) * 4;
            *(float4*)&Vs[r][d4] = *(const float4*)(Vg + (size_t)(kt + r) * HDIM + d4);
        }
        __syncthreads();

        // S = (Q*scale) @ K^T  -> s[4][4]
        float s[4][4];
#pragma unroll
        for (int i = 0; i < 4; i++)
#pragma unroll
            for (int j = 0; j < 4; j++) s[i][j] = 0.f;
#pragma unroll 16
        for (int kk = 0; kk < HDIM; kk++) {
            float4 qv = *(const float4*)&Qs[kk][ty*4];
            float4 kv = *(const float4*)&Ks[kk][tx*4];
            float qr[4] = {qv.x,qv.y,qv.z,qv.w};
            float kr[4] = {kv.x,kv.y,kv.z,kv.w};
#pragma unroll
            for (int i = 0; i < 4; i++)
#pragma unroll
                for (int j = 0; j < 4; j++)
                    s[i][j] = fmaf(qr[i], kr[j], s[i][j]);
        }

        // online softmax (rows split across 16 tx lanes; lane-aligned 16-groups)
#pragma unroll
        for (int i = 0; i < 4; i++) {
            float rmax = fmaxf(fmaxf(s[i][0], s[i][1]), fmaxf(s[i][2], s[i][3]));
#pragma unroll
            for (int ofs = 8; ofs > 0; ofs >>= 1)
                rmax = fmaxf(rmax, __shfl_xor_sync(0xffffffffu, rmax, ofs));
            float mnew  = fmaxf(mrow[i], rmax);
            float alpha = __expf(mrow[i] - mnew);
            float rsum = 0.f;
#pragma unroll
            for (int j = 0; j < 4; j++) {
                s[i][j] = __expf(s[i][j] - mnew);
                rsum += s[i][j];
            }
#pragma unroll
            for (int ofs = 8; ofs > 0; ofs >>= 1)
                rsum += __shfl_xor_sync(0xffffffffu, rsum, ofs);
            lrow[i] = lrow[i] * alpha + rsum;
#pragma unroll
            for (int j = 0; j < 4; j++) o[i][j] *= alpha;
            mrow[i] = mnew;
        }

        // stage P transposed ([k][r])
#pragma unroll
        for (int i = 0; i < 4; i++)
#pragma unroll
            for (int j = 0; j < 4; j++)
                Ps[tx*4+j][ty*4+i] = s[i][j];
        __syncthreads();

        // O += P @ V
#pragma unroll 16
        for (int kk = 0; kk < 64; kk++) {
            float4 pv = *(const float4*)&Ps[kk][ty*4];
            float4 vv = *(const float4*)&Vs[kk][tx*4];
            float pr[4] = {pv.x,pv.y,pv.z,pv.w};
            float vr[4] = {vv.x,vv.y,vv.z,vv.w};
#pragma unroll
            for (int i = 0; i < 4; i++)
#pragma unroll
                for (int j = 0; j < 4; j++)
                    o[i][j] = fmaf(pr[i], vr[j], o[i][j]);
        }
    }

    // epilogue: normalize + write ctx [b][s][h*64+d]
    int b = bh >> 4;
    int h = bh & 15;
#pragma unroll
    for (int i = 0; i < 4; i++) {
        float inv = 1.f / lrow[i];
        int srow = q0 + ty*4 + i;
        size_t base = ((size_t)(b*SEQ + srow))*DIMM + h*HDIM + tx*4;
#pragma unroll
        for (int j = 0; j < 4; j++)
            g_ctx[base + j] = o[i][j] * inv;
    }
}

// ---------------------------------------------------------------------------
extern "C" void kernel_launch(void* const* d_in, const int* in_sizes, int n_in,
                              void* d_out, int out_size)
{
    const float* x      = (const float*)d_in[0];
    const float* qkv_w  = (const float*)d_in[1];
    const float* qkv_b  = (const float*)d_in[2];
    const float* proj_w = (const float*)d_in[3];
    const float* proj_b = (const float*)d_in[4];
    float* out = (float*)d_out;

    (void)in_sizes; (void)n_in; (void)out_size;

    static const int ATTN_SMEM = (3*64*68 + 64*64) * (int)sizeof(float);  // 68608 B
    cudaFuncSetAttribute(attn_kernel, cudaFuncAttributeMaxDynamicSharedMemorySize, ATTN_SMEM);

    dim3 blk(256);
    // 1) QKV projection, scattered into q/k/v scratch
    sgemm_abT<1><<<dim3(3*DIMM/128, MROWS/128), blk>>>(x, qkv_w, qkv_b, nullptr,
                                                       MROWS, 3*DIMM, DIMM);
    // 2) attention
    attn_kernel<<<dim3(SEQ/64, BATCH*NHEADS), blk, ATTN_SMEM>>>();
    // 3) output projection
    sgemm_abT<2><<<dim3(DIMM/128, MROWS/128), blk>>>(nullptr, proj_w, proj_b, out,
                                                     MROWS, DIMM, DIMM);
}